// round 16
// baseline (speedup 1.0000x reference)
#include <cuda_runtime.h>
#include <cuda_bf16.h>
#include <math.h>
#include <stdint.h>

// Problem constants
#define BATCH 4
#define SEQ   2048
#define NH    16
#define HD    64
#define HID   1024           // NH*HD
#define MROWS (BATCH*SEQ)    // 8192

// ---------------------------------------------------------------------------
// mma.sync m16n8k16 bf16 (arch-portable HMMA; tcgen05 unavailable: harness
// targets family-generic sm_103, not sm_103a)
// ---------------------------------------------------------------------------
#define MMA16816(d, a, b) \
    asm volatile("mma.sync.aligned.m16n8k16.row.col.f32.bf16.bf16.f32 " \
        "{%0,%1,%2,%3}, {%4,%5,%6,%7}, {%8,%9}, {%0,%1,%2,%3};" \
        : "+f"((d)[0]), "+f"((d)[1]), "+f"((d)[2]), "+f"((d)[3]) \
        : "r"((a)[0]), "r"((a)[1]), "r"((a)[2]), "r"((a)[3]), \
          "r"((b)[0]), "r"((b)[1]))

__device__ __forceinline__ uint32_t smem_u32(const void* p) {
    uint32_t a;
    asm("{ .reg .u64 t; cvta.to.shared.u64 t, %1; cvt.u32.u64 %0, t; }"
        : "=r"(a) : "l"(p));
    return a;
}
__device__ __forceinline__ void cpa16(uint32_t s, const void* g) {
    asm volatile("cp.async.cg.shared.global [%0], [%1], 16;" :: "r"(s), "l"(g));
}
__device__ __forceinline__ void cp_commit() {
    asm volatile("cp.async.commit_group;" ::: "memory");
}
template<int N> __device__ __forceinline__ void cp_wait() {
    asm volatile("cp.async.wait_group %0;" :: "n"(N) : "memory");
}

// Split two fp32 into packed bf16 hi-pair and lo-pair (residual)
__device__ __forceinline__ void split_pack(float x, float y,
                                           uint32_t& hp, uint32_t& lp) {
    __nv_bfloat16 hx = __float2bfloat16(x);
    __nv_bfloat16 hy = __float2bfloat16(y);
    __nv_bfloat16 lx = __float2bfloat16(x - __bfloat162float(hx));
    __nv_bfloat16 ly = __float2bfloat16(y - __bfloat162float(hy));
    __nv_bfloat162 H; H.x = hx; H.y = hy;
    __nv_bfloat162 L; L.x = lx; L.y = ly;
    hp = *reinterpret_cast<uint32_t*>(&H);
    lp = *reinterpret_cast<uint32_t*>(&L);
}

// ---------------------------------------------------------------------------
// Scratch (allocation-free)
// ---------------------------------------------------------------------------
__device__ float g_v[MROWS * HID];
__device__ __nv_bfloat16 g_xh[MROWS * HID];
__device__ __nv_bfloat16 g_xl[MROWS * HID];
__device__ __nv_bfloat16 g_wh[4 * HID * HID];
__device__ __nv_bfloat16 g_wl[4 * HID * HID];
__device__ __nv_bfloat16 g_ah[MROWS * HID];
__device__ __nv_bfloat16 g_al[MROWS * HID];
__device__ __nv_bfloat16 g_qh[MROWS * HID];
__device__ __nv_bfloat16 g_ql[MROWS * HID];
__device__ __nv_bfloat16 g_kh[MROWS * HID];
__device__ __nv_bfloat16 g_kl[MROWS * HID];
__device__ __nv_bfloat16 g_vh[MROWS * HID];   // V^T hi: [b][h][d][t]
__device__ __nv_bfloat16 g_vl[MROWS * HID];   // V^T lo: [b][h][d][t]

// ---------------------------------------------------------------------------
// Merged split: x (8192 blocks) + wq/wk/wv/wo (1024 blocks each) in ONE launch
// ---------------------------------------------------------------------------
__global__ void split_all(const float* __restrict__ x,
                          const float* __restrict__ wq, const float* __restrict__ wk,
                          const float* __restrict__ wv, const float* __restrict__ wo,
                          __nv_bfloat16* __restrict__ xh, __nv_bfloat16* __restrict__ xl,
                          __nv_bfloat16* __restrict__ wh, __nv_bfloat16* __restrict__ wl) {
    int blk = blockIdx.x;
    const float* src;
    __nv_bfloat16 *hi, *lo;
    int i;
    if (blk < 8192) {
        src = x; hi = xh; lo = xl;
        i = blk * 256 + threadIdx.x;
    } else {
        int r  = (blk - 8192) >> 10;          // 0..3
        int bb = (blk - 8192) & 1023;
        src = (r == 0) ? wq : (r == 1) ? wk : (r == 2) ? wv : wo;
        hi = wh + (size_t)r * HID * HID;
        lo = wl + (size_t)r * HID * HID;
        i = bb * 256 + threadIdx.x;
    }
    float4 f = reinterpret_cast<const float4*>(src)[i];
    __nv_bfloat16 h0 = __float2bfloat16(f.x);
    __nv_bfloat16 h1 = __float2bfloat16(f.y);
    __nv_bfloat16 h2 = __float2bfloat16(f.z);
    __nv_bfloat16 h3 = __float2bfloat16(f.w);
    __nv_bfloat16 l0 = __float2bfloat16(f.x - __bfloat162float(h0));
    __nv_bfloat16 l1 = __float2bfloat16(f.y - __bfloat162float(h1));
    __nv_bfloat16 l2 = __float2bfloat16(f.z - __bfloat162float(h2));
    __nv_bfloat16 l3 = __float2bfloat16(f.w - __bfloat162float(h3));
    __nv_bfloat162 hp0; hp0.x = h0; hp0.y = h1;
    __nv_bfloat162 hp1; hp1.x = h2; hp1.y = h3;
    __nv_bfloat162 lp0; lp0.x = l0; lp0.y = l1;
    __nv_bfloat162 lp1; lp1.x = l2; lp1.y = l3;
    reinterpret_cast<__nv_bfloat162*>(hi)[i * 2 + 0] = hp0;
    reinterpret_cast<__nv_bfloat162*>(hi)[i * 2 + 1] = hp1;
    reinterpret_cast<__nv_bfloat162*>(lo)[i * 2 + 0] = lp0;
    reinterpret_cast<__nv_bfloat162*>(lo)[i * 2 + 1] = lp1;
}

// ---------------------------------------------------------------------------
// V transpose + split: v[b,t,h*64+d] fp32 -> vT[b,h,d,t] bf16 hi/lo
// ---------------------------------------------------------------------------
__global__ void vsplit_t(const float* __restrict__ v,
                         __nv_bfloat16* __restrict__ hT,
                         __nv_bfloat16* __restrict__ lT) {
    __shared__ float tile[32][33];
    int bhid = blockIdx.z;
    int b = bhid >> 4, h = bhid & 15;
    int t0 = blockIdx.x * 32;
    int d0 = blockIdx.y * 32;
    int tx = threadIdx.x;
    int ty = threadIdx.y;
#pragma unroll
    for (int i = 0; i < 4; i++) {
        int t = t0 + ty + i * 8;
        tile[ty + i * 8][tx] = v[((size_t)(b * SEQ + t)) * HID + h * HD + d0 + tx];
    }
    __syncthreads();
#pragma unroll
    for (int i = 0; i < 4; i++) {
        int d = d0 + ty + i * 8;
        float f = tile[tx][ty + i * 8];
        __nv_bfloat16 hi = __float2bfloat16(f);
        size_t o = ((size_t)bhid * HD + d) * SEQ + t0 + tx;
        hT[o] = hi;
        lT[o] = __float2bfloat16(f - __bfloat162float(hi));
    }
}

// ---------------------------------------------------------------------------
// Shared GEMM mainloop (macro-expanded into both kernels).
// Block 128x128, BK=32, 8 warps 4(m)x2(n), cp.async double-buffered.
// ---------------------------------------------------------------------------
#define GK 1024
#define GN 1024
#define LDSB 40
#define TILEG (128 * LDSB)                    // halves per tile
#define GEMM_SMEM (2 * 4 * TILEG * 2)         // bytes (2 stages x 4 tiles)

#define GEMM_MAINLOOP(acc, AhP, AlP, BhP, BlP)                                  \
    const __nv_bfloat16* gsrc[4] = {AhP + (size_t)m0 * GK, AlP + (size_t)m0 * GK,\
                                    BhP + (size_t)n0 * GK, BlP + (size_t)n0 * GK};\
    auto issue = [&](int k0, int buf) {                                         \
        uint32_t b0 = sbase + (uint32_t)buf * 4 * TILEG * 2;                    \
        for (int s = tid; s < 512; s += 256) {                                  \
            int r = s >> 2;                                                     \
            int c = (s & 3) * 8;                                                \
            uint32_t doff = (uint32_t)(r * LDSB + c) * 2;                       \
            _Pragma("unroll")                                                   \
            for (int t = 0; t < 4; t++)                                         \
                cpa16(b0 + (uint32_t)t * TILEG * 2 + doff,                      \
                      gsrc[t] + (size_t)r * GK + k0 + c);                       \
        }                                                                       \
        cp_commit();                                                            \
    };                                                                          \
    issue(0, 0);                                                                \
    for (int kt = 0; kt < 32; kt++) {                                           \
        if (kt < 31) issue((kt + 1) * 32, (kt + 1) & 1);                        \
        if (kt < 31) cp_wait<1>(); else cp_wait<0>();                           \
        __syncthreads();                                                        \
        __nv_bfloat16* sAh = dsm + (size_t)(kt & 1) * 4 * TILEG;                \
        __nv_bfloat16* sAl = sAh + TILEG;                                       \
        __nv_bfloat16* sBh = sAh + 2 * TILEG;                                   \
        __nv_bfloat16* sBl = sAh + 3 * TILEG;                                   \
        _Pragma("unroll")                                                       \
        for (int kk = 0; kk < 32; kk += 16) {                                   \
            uint32_t ah[2][4], al[2][4], bh[8][2], bl[8][2];                    \
            _Pragma("unroll")                                                   \
            for (int mf = 0; mf < 2; mf++) {                                    \
                int row = mbase + mf * 16 + g;                                  \
                int col = kk + tig * 2;                                         \
                ah[mf][0] = *reinterpret_cast<uint32_t*>(&sAh[row * LDSB + col]);\
                ah[mf][1] = *reinterpret_cast<uint32_t*>(&sAh[(row + 8) * LDSB + col]);\
                ah[mf][2] = *reinterpret_cast<uint32_t*>(&sAh[row * LDSB + col + 8]);\
                ah[mf][3] = *reinterpret_cast<uint32_t*>(&sAh[(row + 8) * LDSB + col + 8]);\
                al[mf][0] = *reinterpret_cast<uint32_t*>(&sAl[row * LDSB + col]);\
                al[mf][1] = *reinterpret_cast<uint32_t*>(&sAl[(row + 8) * LDSB + col]);\
                al[mf][2] = *reinterpret_cast<uint32_t*>(&sAl[row * LDSB + col + 8]);\
                al[mf][3] = *reinterpret_cast<uint32_t*>(&sAl[(row + 8) * LDSB + col + 8]);\
            }                                                                   \
            _Pragma("unroll")                                                   \
            for (int nf = 0; nf < 8; nf++) {                                    \
                int row = nbase + nf * 8 + g;                                   \
                int col = kk + tig * 2;                                         \
                bh[nf][0] = *reinterpret_cast<uint32_t*>(&sBh[row * LDSB + col]);\
                bh[nf][1] = *reinterpret_cast<uint32_t*>(&sBh[row * LDSB + col + 8]);\
                bl[nf][0] = *reinterpret_cast<uint32_t*>(&sBl[row * LDSB + col]);\
                bl[nf][1] = *reinterpret_cast<uint32_t*>(&sBl[row * LDSB + col + 8]);\
            }                                                                   \
            _Pragma("unroll")                                                   \
            for (int mf = 0; mf < 2; mf++)                                      \
                _Pragma("unroll")                                               \
                for (int nf = 0; nf < 8; nf++) {                                \
                    MMA16816(acc[mf][nf], ah[mf], bh[nf]);                      \
                    MMA16816(acc[mf][nf], ah[mf], bl[nf]);                      \
                    MMA16816(acc[mf][nf], al[mf], bh[nf]);                      \
                }                                                               \
        }                                                                       \
        __syncthreads();                                                        \
    }

// ---------------------------------------------------------------------------
// Merged Q/K/V projection: grid.z selects weight + epilogue.
// z=0: Q rope+scale+split; z=1: K rope+split; z=2: V fp32.
// ---------------------------------------------------------------------------
__global__ void __launch_bounds__(256) gemm_qkv(
        const __nv_bfloat16* __restrict__ Ah, const __nv_bfloat16* __restrict__ Al,
        const __nv_bfloat16* __restrict__ Wh, const __nv_bfloat16* __restrict__ Wl,
        __nv_bfloat16* __restrict__ Qh, __nv_bfloat16* __restrict__ Ql,
        __nv_bfloat16* __restrict__ Kh, __nv_bfloat16* __restrict__ Kl,
        float* __restrict__ V,
        const float* __restrict__ cosT, const float* __restrict__ sinT) {
    extern __shared__ __nv_bfloat16 dsm[];
    const uint32_t sbase = smem_u32(dsm);

    const int tid  = threadIdx.x;
    const int warp = tid >> 5;
    const int lane = tid & 31;
    const int g    = lane >> 2;
    const int tig  = lane & 3;
    const int z    = blockIdx.z;

    const int m0 = blockIdx.y * 128;
    const int n0 = blockIdx.x * 128;
    const int mbase = (warp & 3) * 32;
    const int nbase = (warp >> 2) * 64;

    const __nv_bfloat16* Bh = Wh + (size_t)z * HID * HID;
    const __nv_bfloat16* Bl = Wl + (size_t)z * HID * HID;

    float acc[2][8][4];
#pragma unroll
    for (int mf = 0; mf < 2; mf++)
#pragma unroll
        for (int nf = 0; nf < 8; nf++)
#pragma unroll
            for (int c = 0; c < 4; c++) acc[mf][nf][c] = 0.f;

    GEMM_MAINLOOP(acc, Ah, Al, Bh, Bl)

    if (z == 2) {
#pragma unroll
        for (int mf = 0; mf < 2; mf++) {
#pragma unroll
            for (int nf = 0; nf < 8; nf++) {
                int row = m0 + mbase + mf * 16 + g;
                int col = n0 + nbase + nf * 8 + tig * 2;
                *reinterpret_cast<float2*>(V + (size_t)row * GN + col) =
                    make_float2(acc[mf][nf][0], acc[mf][nf][1]);
                *reinterpret_cast<float2*>(V + (size_t)(row + 8) * GN + col) =
                    make_float2(acc[mf][nf][2], acc[mf][nf][3]);
            }
        }
    } else {
        __nv_bfloat16* Oh = (z == 0) ? Qh : Kh;
        __nv_bfloat16* Ol = (z == 0) ? Ql : Kl;
        float scale = (z == 0) ? 0.125f : 1.0f;
#pragma unroll
        for (int mf = 0; mf < 2; mf++) {
            int r0 = m0 + mbase + mf * 16 + g;
            int r1 = r0 + 8;
            int t0 = r0 & (SEQ - 1);
            int t1 = r1 & (SEQ - 1);
#pragma unroll
            for (int nf = 0; nf < 4; nf++) {
                int d = nf * 8 + tig * 2;           // head-local, < 32, even
                int col = n0 + nbase + d;
                float2 ca = *reinterpret_cast<const float2*>(&cosT[t0 * HD + d]);
                float2 sa = *reinterpret_cast<const float2*>(&sinT[t0 * HD + d]);
                float2 cb = *reinterpret_cast<const float2*>(&cosT[t1 * HD + d]);
                float2 sb = *reinterpret_cast<const float2*>(&sinT[t1 * HD + d]);
                float* a = acc[mf][nf];
                float* b = acc[mf][nf + 4];
                uint32_t hp, lp;
                split_pack((a[0] * ca.x - b[0] * sa.x) * scale,
                           (a[1] * ca.y - b[1] * sa.y) * scale, hp, lp);
                *reinterpret_cast<uint32_t*>(&Oh[(size_t)r0 * HID + col]) = hp;
                *reinterpret_cast<uint32_t*>(&Ol[(size_t)r0 * HID + col]) = lp;
                split_pack((b[0] * ca.x + a[0] * sa.x) * scale,
                           (b[1] * ca.y + a[1] * sa.y) * scale, hp, lp);
                *reinterpret_cast<uint32_t*>(&Oh[(size_t)r0 * HID + col + 32]) = hp;
                *reinterpret_cast<uint32_t*>(&Ol[(size_t)r0 * HID + col + 32]) = lp;
                split_pack((a[2] * cb.x - b[2] * sb.x) * scale,
                           (a[3] * cb.y - b[3] * sb.y) * scale, hp, lp);
                *reinterpret_cast<uint32_t*>(&Oh[(size_t)r1 * HID + col]) = hp;
                *reinterpret_cast<uint32_t*>(&Ol[(size_t)r1 * HID + col]) = lp;
                split_pack((b[2] * cb.x + a[2] * sb.x) * scale,
                           (b[3] * cb.y + a[3] * sb.y) * scale, hp, lp);
                *reinterpret_cast<uint32_t*>(&Oh[(size_t)r1 * HID + col + 32]) = hp;
                *reinterpret_cast<uint32_t*>(&Ol[(size_t)r1 * HID + col + 32]) = lp;
            }
        }
    }
}

// ---------------------------------------------------------------------------
// Output projection: plain fp32 C epilogue
// ---------------------------------------------------------------------------
__global__ void __launch_bounds__(256) gemm_out(
        const __nv_bfloat16* __restrict__ Ah, const __nv_bfloat16* __restrict__ Al,
        const __nv_bfloat16* __restrict__ Bh, const __nv_bfloat16* __restrict__ Bl,
        float* __restrict__ C) {
    extern __shared__ __nv_bfloat16 dsm[];
    const uint32_t sbase = smem_u32(dsm);

    const int tid  = threadIdx.x;
    const int warp = tid >> 5;
    const int lane = tid & 31;
    const int g    = lane >> 2;
    const int tig  = lane & 3;

    const int m0 = blockIdx.y * 128;
    const int n0 = blockIdx.x * 128;
    const int mbase = (warp & 3) * 32;
    const int nbase = (warp >> 2) * 64;

    float acc[2][8][4];
#pragma unroll
    for (int mf = 0; mf < 2; mf++)
#pragma unroll
        for (int nf = 0; nf < 8; nf++)
#pragma unroll
            for (int c = 0; c < 4; c++) acc[mf][nf][c] = 0.f;

    GEMM_MAINLOOP(acc, Ah, Al, Bh, Bl)

#pragma unroll
    for (int mf = 0; mf < 2; mf++) {
#pragma unroll
        for (int nf = 0; nf < 8; nf++) {
            int row = m0 + mbase + mf * 16 + g;
            int col = n0 + nbase + nf * 8 + tig * 2;
            *reinterpret_cast<float2*>(C + (size_t)row * GN + col) =
                make_float2(acc[mf][nf][0], acc[mf][nf][1]);
            *reinterpret_cast<float2*>(C + (size_t)(row + 8) * GN + col) =
                make_float2(acc[mf][nf][2], acc[mf][nf][3]);
        }
    }
}

// ---------------------------------------------------------------------------
// HMMA flash attention: 64-query tile, 4 warps (proven R13 shape), causal,
// double-buffered cp.async K/V^T, heavy-first order, split-bf16 output.
// ---------------------------------------------------------------------------
#define AT_STR 72
#define TILEA (64 * AT_STR)                   // halves per 64-row tile
#define FLASH_SMEM (2 * 4 * TILEA * 2)        // bytes (2 stages x 4 tiles)

__global__ void __launch_bounds__(128) flash_mma(
        const __nv_bfloat16* __restrict__ qh, const __nv_bfloat16* __restrict__ ql,
        const __nv_bfloat16* __restrict__ kh, const __nv_bfloat16* __restrict__ kl,
        const __nv_bfloat16* __restrict__ vhT, const __nv_bfloat16* __restrict__ vlT,
        __nv_bfloat16* __restrict__ oh, __nv_bfloat16* __restrict__ ol) {
    extern __shared__ __nv_bfloat16 fsm[];
    const uint32_t sbase = smem_u32(fsm);

    const int qt = (gridDim.x - 1) - blockIdx.x;   // heavy blocks first
    const int bhid = blockIdx.y;
    const int b = bhid >> 4;
    const int h = bhid & 15;
    const int tid = threadIdx.x;
    const int w = tid >> 5;
    const int lane = tid & 31;
    const int g = lane >> 2;
    const int tig = lane & 3;

    const size_t baseQ  = ((size_t)b * SEQ + qt * 64) * HID + h * HD;
    const size_t baseKV = (size_t)b * SEQ * HID + h * HD;
    const size_t baseVT = (size_t)bhid * HD * SEQ;

    // Stage Q (64 x 64) into stage-0 region, extract persistent frags
    {
        __nv_bfloat16* sQh = fsm;
        __nv_bfloat16* sQl = fsm + TILEA;
        for (int s = tid; s < 512; s += 128) {
            int r = s >> 3;
            int c8 = (s & 7) * 8;
            *reinterpret_cast<uint4*>(&sQh[r * AT_STR + c8]) =
                *reinterpret_cast<const uint4*>(qh + baseQ + (size_t)r * HID + c8);
            *reinterpret_cast<uint4*>(&sQl[r * AT_STR + c8]) =
                *reinterpret_cast<const uint4*>(ql + baseQ + (size_t)r * HID + c8);
        }
    }
    __syncthreads();

    uint32_t qfh[4][4], qfl[4][4];
    {
        __nv_bfloat16* sQh = fsm;
        __nv_bfloat16* sQl = fsm + TILEA;
        int row = w * 16 + g;
#pragma unroll
        for (int kc = 0; kc < 4; kc++) {
            int c = kc * 16 + tig * 2;
            qfh[kc][0] = *reinterpret_cast<uint32_t*>(&sQh[row * AT_STR + c]);
            qfh[kc][1] = *reinterpret_cast<uint32_t*>(&sQh[(row + 8) * AT_STR + c]);
            qfh[kc][2] = *reinterpret_cast<uint32_t*>(&sQh[row * AT_STR + c + 8]);
            qfh[kc][3] = *reinterpret_cast<uint32_t*>(&sQh[(row + 8) * AT_STR + c + 8]);
            qfl[kc][0] = *reinterpret_cast<uint32_t*>(&sQl[row * AT_STR + c]);
            qfl[kc][1] = *reinterpret_cast<uint32_t*>(&sQl[(row + 8) * AT_STR + c]);
            qfl[kc][2] = *reinterpret_cast<uint32_t*>(&sQl[row * AT_STR + c + 8]);
            qfl[kc][3] = *reinterpret_cast<uint32_t*>(&sQl[(row + 8) * AT_STR + c + 8]);
        }
    }
    __syncthreads();

    auto issue = [&](int jt, int buf) {
        uint32_t b0 = sbase + (uint32_t)buf * 4 * TILEA * 2;
        const __nv_bfloat16* kbh = kh + baseKV + (size_t)jt * 64 * HID;
        const __nv_bfloat16* kbl = kl + baseKV + (size_t)jt * 64 * HID;
        const __nv_bfloat16* vbh = vhT + baseVT + jt * 64;
        const __nv_bfloat16* vbl = vlT + baseVT + jt * 64;
        for (int s = tid; s < 512; s += 128) {
            int r = s >> 3;
            int c8 = (s & 7) * 8;
            uint32_t doff = (uint32_t)(r * AT_STR + c8) * 2;
            cpa16(b0 + 0u * TILEA * 2 + doff, kbh + (size_t)r * HID + c8);
            cpa16(b0 + 1u * TILEA * 2 + doff, kbl + (size_t)r * HID + c8);
            cpa16(b0 + 2u * TILEA * 2 + doff, vbh + (size_t)r * SEQ + c8);
            cpa16(b0 + 3u * TILEA * 2 + doff, vbl + (size_t)r * SEQ + c8);
        }
        cp_commit();
    };

    float O[8][4];
#pragma unroll
    for (int nf = 0; nf < 8; nf++)
#pragma unroll
        for (int c = 0; c < 4; c++) O[nf][c] = 0.f;
    float m0 = -INFINITY, m1 = -INFINITY, l0 = 0.f, l1 = 0.f;

    issue(0, 0);

    for (int jt = 0; jt <= qt; jt++) {
        if (jt < qt) issue(jt + 1, (jt + 1) & 1);
        if (jt < qt) cp_wait<1>(); else cp_wait<0>();
        __syncthreads();

        __nv_bfloat16* sKh = fsm + (size_t)(jt & 1) * 4 * TILEA;
        __nv_bfloat16* sKl = sKh + TILEA;
        __nv_bfloat16* sVh = sKh + 2 * TILEA;
        __nv_bfloat16* sVl = sKh + 3 * TILEA;

        // S = Q K^T (16x64 per warp), 3-pass split
        float S[8][4];
#pragma unroll
        for (int nf = 0; nf < 8; nf++)
#pragma unroll
            for (int c = 0; c < 4; c++) S[nf][c] = 0.f;

#pragma unroll
        for (int nf = 0; nf < 8; nf++) {
            int rowb = nf * 8 + g;
#pragma unroll
            for (int kc = 0; kc < 4; kc++) {
                int c = kc * 16 + tig * 2;
                uint32_t bkh[2], bkl[2];
                bkh[0] = *reinterpret_cast<uint32_t*>(&sKh[rowb * AT_STR + c]);
                bkh[1] = *reinterpret_cast<uint32_t*>(&sKh[rowb * AT_STR + c + 8]);
                bkl[0] = *reinterpret_cast<uint32_t*>(&sKl[rowb * AT_STR + c]);
                bkl[1] = *reinterpret_cast<uint32_t*>(&sKl[rowb * AT_STR + c + 8]);
                MMA16816(S[nf], qfh[kc], bkh);
                MMA16816(S[nf], qfh[kc], bkl);
                MMA16816(S[nf], qfl[kc], bkh);
            }
        }

        if (jt == qt) {
            int lr0 = w * 16 + g;
            int lr1 = lr0 + 8;
#pragma unroll
            for (int nf = 0; nf < 8; nf++) {
                int jc = nf * 8 + tig * 2;
                if (jc > lr0)     S[nf][0] = -INFINITY;
                if (jc + 1 > lr0) S[nf][1] = -INFINITY;
                if (jc > lr1)     S[nf][2] = -INFINITY;
                if (jc + 1 > lr1) S[nf][3] = -INFINITY;
            }
        }

        // Online softmax (quad shfl)
        float mx0 = -INFINITY, mx1 = -INFINITY;
#pragma unroll
        for (int nf = 0; nf < 8; nf++) {
            mx0 = fmaxf(mx0, fmaxf(S[nf][0], S[nf][1]));
            mx1 = fmaxf(mx1, fmaxf(S[nf][2], S[nf][3]));
        }
        mx0 = fmaxf(mx0, __shfl_xor_sync(0xFFFFFFFF, mx0, 1));
        mx0 = fmaxf(mx0, __shfl_xor_sync(0xFFFFFFFF, mx0, 2));
        mx1 = fmaxf(mx1, __shfl_xor_sync(0xFFFFFFFF, mx1, 1));
        mx1 = fmaxf(mx1, __shfl_xor_sync(0xFFFFFFFF, mx1, 2));
        float nm0 = fmaxf(m0, mx0);
        float nm1 = fmaxf(m1, mx1);
        float corr0 = __expf(m0 - nm0);
        float corr1 = __expf(m1 - nm1);
        m0 = nm0; m1 = nm1;
        float sum0 = 0.f, sum1 = 0.f;
#pragma unroll
        for (int nf = 0; nf < 8; nf++) {
            S[nf][0] = __expf(S[nf][0] - m0); sum0 += S[nf][0];
            S[nf][1] = __expf(S[nf][1] - m0); sum0 += S[nf][1];
            S[nf][2] = __expf(S[nf][2] - m1); sum1 += S[nf][2];
            S[nf][3] = __expf(S[nf][3] - m1); sum1 += S[nf][3];
        }
        sum0 += __shfl_xor_sync(0xFFFFFFFF, sum0, 1);
        sum0 += __shfl_xor_sync(0xFFFFFFFF, sum0, 2);
        sum1 += __shfl_xor_sync(0xFFFFFFFF, sum1, 1);
        sum1 += __shfl_xor_sync(0xFFFFFFFF, sum1, 2);
        l0 = l0 * corr0 + sum0;
        l1 = l1 * corr1 + sum1;
#pragma unroll
        for (int nf = 0; nf < 8; nf++) {
            O[nf][0] *= corr0; O[nf][1] *= corr0;
            O[nf][2] *= corr1; O[nf][3] *= corr1;
        }

        // S (C-frag) -> P A-frags (hi/lo) in registers
        uint32_t aPh[4][4], aPl[4][4];
#pragma unroll
        for (int kc = 0; kc < 4; kc++) {
            split_pack(S[2 * kc][0],     S[2 * kc][1],     aPh[kc][0], aPl[kc][0]);
            split_pack(S[2 * kc][2],     S[2 * kc][3],     aPh[kc][1], aPl[kc][1]);
            split_pack(S[2 * kc + 1][0], S[2 * kc + 1][1], aPh[kc][2], aPl[kc][2]);
            split_pack(S[2 * kc + 1][2], S[2 * kc + 1][3], aPh[kc][3], aPl[kc][3]);
        }

        // O += P @ V (V^T tiles), 3-pass split
#pragma unroll
        for (int nf = 0; nf < 8; nf++) {
            int rowb = nf * 8 + g;
#pragma unroll
            for (int kc = 0; kc < 4; kc++) {
                int c = kc * 16 + tig * 2;
                uint32_t bvh[2], bvl[2];
                bvh[0] = *reinterpret_cast<uint32_t*>(&sVh[rowb * AT_STR + c]);
                bvh[1] = *reinterpret_cast<uint32_t*>(&sVh[rowb * AT_STR + c + 8]);
                bvl[0] = *reinterpret_cast<uint32_t*>(&sVl[rowb * AT_STR + c]);
                bvl[1] = *reinterpret_cast<uint32_t*>(&sVl[rowb * AT_STR + c + 8]);
                MMA16816(O[nf], aPh[kc], bvh);
                MMA16816(O[nf], aPh[kc], bvl);
                MMA16816(O[nf], aPl[kc], bvh);
            }
        }
        __syncthreads();
    }

    // Normalize + split-bf16 write (feeds output GEMM directly)
    float inv0 = 1.f / l0;
    float inv1 = 1.f / l1;
    int row0 = qt * 64 + w * 16 + g;
#pragma unroll
    for (int nf = 0; nf < 8; nf++) {
        int col = nf * 8 + tig * 2;
        uint32_t hp, lp;
        size_t o0 = ((size_t)b * SEQ + row0) * HID + h * HD + col;
        size_t o1 = ((size_t)b * SEQ + row0 + 8) * HID + h * HD + col;
        split_pack(O[nf][0] * inv0, O[nf][1] * inv0, hp, lp);
        *reinterpret_cast<uint32_t*>(&oh[o0]) = hp;
        *reinterpret_cast<uint32_t*>(&ol[o0]) = lp;
        split_pack(O[nf][2] * inv1, O[nf][3] * inv1, hp, lp);
        *reinterpret_cast<uint32_t*>(&oh[o1]) = hp;
        *reinterpret_cast<uint32_t*>(&ol[o1]) = lp;
    }
}

// ---------------------------------------------------------------------------
// Launch
// ---------------------------------------------------------------------------
extern "C" void kernel_launch(void* const* d_in, const int* in_sizes, int n_in,
                              void* d_out, int out_size) {
    const float* x    = (const float*)d_in[0];
    const float* cosT = (const float*)d_in[1];
    const float* sinT = (const float*)d_in[2];
    const float* wq   = (const float*)d_in[3];
    const float* wk   = (const float*)d_in[4];
    const float* wv   = (const float*)d_in[5];
    const float* wo   = (const float*)d_in[6];
    float* out = (float*)d_out;

    float* v;
    __nv_bfloat16 *xh, *xl, *wh, *wl, *ah, *al;
    __nv_bfloat16 *qhp, *qlp, *khp, *klp, *vhp, *vlp;
    cudaGetSymbolAddress((void**)&v, g_v);
    cudaGetSymbolAddress((void**)&xh, g_xh);
    cudaGetSymbolAddress((void**)&xl, g_xl);
    cudaGetSymbolAddress((void**)&wh, g_wh);
    cudaGetSymbolAddress((void**)&wl, g_wl);
    cudaGetSymbolAddress((void**)&ah, g_ah);
    cudaGetSymbolAddress((void**)&al, g_al);
    cudaGetSymbolAddress((void**)&qhp, g_qh);
    cudaGetSymbolAddress((void**)&qlp, g_ql);
    cudaGetSymbolAddress((void**)&khp, g_kh);
    cudaGetSymbolAddress((void**)&klp, g_kl);
    cudaGetSymbolAddress((void**)&vhp, g_vh);
    cudaGetSymbolAddress((void**)&vlp, g_vl);

    cudaFuncSetAttribute(gemm_qkv, cudaFuncAttributeMaxDynamicSharedMemorySize,
                         GEMM_SMEM);
    cudaFuncSetAttribute(gemm_out, cudaFuncAttributeMaxDynamicSharedMemorySize,
                         GEMM_SMEM);
    cudaFuncSetAttribute(flash_mma, cudaFuncAttributeMaxDynamicSharedMemorySize,
                         FLASH_SMEM);

    // One merged split launch: x + 4 weights
    split_all<<<8192 + 4096, 256>>>(x, wq, wk, wv, wo, xh, xl, wh, wl);

    // Merged Q/K/V projections (z selects weight + epilogue)
    dim3 qkvgrid(HID / 128, MROWS / 128, 3);   // (8, 64, 3)
    gemm_qkv<<<qkvgrid, 256, GEMM_SMEM>>>(xh, xl, wh, wl,
                                          qhp, qlp, khp, klp, v, cosT, sinT);

    // V transpose + split
    vsplit_t<<<dim3(SEQ / 32, HD / 32, BATCH * NH), dim3(32, 8)>>>(v, vhp, vlp);

    // Flash attention (64q tile, heavy-first), split-bf16 out
    dim3 fgrid(SEQ / 64, BATCH * NH);          // (32, 64)
    flash_mma<<<fgrid, 128, FLASH_SMEM>>>(qhp, qlp, khp, klp, vhp, vlp, ah, al);

    // Output projection
    dim3 ogrid(HID / 128, MROWS / 128);        // (8, 64)
    gemm_out<<<ogrid, 256, GEMM_SMEM>>>(ah, al, wh + 3 * (size_t)HID * HID,
                                        wl + 3 * (size_t)HID * HID, out);
}